// round 2
// baseline (speedup 1.0000x reference)
#include <cuda_runtime.h>
#include <cuda_bf16.h>

// Problem constants (from reference): PATCH_DIM=768, EMBED_DIM=256, COORD_DIM=3.
// Key insight: the unflatten->aggregate->reflatten round-trip is the identity on
// the T valid tokens, and every stage is linear. Therefore:
//   depth[t] = dot(patches[t], W_tok @ W_depth)
//            + dot(coords[t],  W_pos @ W_depth)
//            + (b_tok + b_pos) . W_depth + b_depth
// Precompute the folded vectors once (kernel 1), then stream patches (kernel 2).

#define PATCH_DIM 768
#define EMBED_DIM 256

// Scratch for folded weights (no cudaMalloc allowed).
__device__ float g_vtok[PATCH_DIM];
__device__ float g_vpos[3];
__device__ float g_bias;

__global__ void fold_weights_kernel(const float* __restrict__ W_tok,
                                    const float* __restrict__ b_tok,
                                    const float* __restrict__ W_pos,
                                    const float* __restrict__ b_pos,
                                    const float* __restrict__ W_dep,
                                    const float* __restrict__ b_dep) {
    int r = blockIdx.x * blockDim.x + threadIdx.x;
    if (r < PATCH_DIM) {
        const float* row = W_tok + (size_t)r * EMBED_DIM;
        float s = 0.f;
        #pragma unroll 8
        for (int e = 0; e < EMBED_DIM; ++e) s = fmaf(row[e], W_dep[e], s);
        g_vtok[r] = s;
    }
    if (r < 3) {
        const float* row = W_pos + (size_t)r * EMBED_DIM;
        float s = 0.f;
        #pragma unroll 8
        for (int e = 0; e < EMBED_DIM; ++e) s = fmaf(row[e], W_dep[e], s);
        g_vpos[r] = s;
    }
    if (r == 0) {
        float s = 0.f;
        for (int e = 0; e < EMBED_DIM; ++e) s = fmaf(b_tok[e] + b_pos[e], W_dep[e], s);
        g_bias = s + b_dep[0];
    }
}

// One warp per token. 768 floats/row = 192 float4; 6 float4 per lane,
// lane-contiguous so every iteration is a coalesced 512B segment.
__global__ __launch_bounds__(256, 8)
void depth_kernel(const float* __restrict__ patches,
                  const float* __restrict__ coords,
                  float* __restrict__ out,
                  int T) {
    int warp = (int)((blockIdx.x * blockDim.x + threadIdx.x) >> 5);
    int lane = threadIdx.x & 31;
    if (warp >= T) return;

    const float4* p = (const float4*)(patches + (size_t)warp * PATCH_DIM);
    const float4* v = (const float4*)g_vtok;

    float s = 0.f;
    #pragma unroll
    for (int j = 0; j < PATCH_DIM / (4 * 32); ++j) {
        float4 a = p[lane + 32 * j];
        float4 b = v[lane + 32 * j];
        s = fmaf(a.x, b.x, s);
        s = fmaf(a.y, b.y, s);
        s = fmaf(a.z, b.z, s);
        s = fmaf(a.w, b.w, s);
    }
    // warp tree reduce
    #pragma unroll
    for (int off = 16; off > 0; off >>= 1)
        s += __shfl_xor_sync(0xffffffffu, s, off);

    if (lane == 0) {
        const float* c3 = coords + 3 * (size_t)warp;
        float r = s
                + c3[0] * g_vpos[0]
                + c3[1] * g_vpos[1]
                + c3[2] * g_vpos[2]
                + g_bias;
        out[warp] = r;
    }
}

extern "C" void kernel_launch(void* const* d_in, const int* in_sizes, int n_in,
                              void* d_out, int out_size) {
    // metadata order (setup_inputs dict order):
    // 0 counts [N,S] int  (unused — ragged indices are identity round-trip)
    // 1 all_coords  [T,3]   f32
    // 2 all_patches [T,768] f32
    // 3 W_tok [768,256] f32
    // 4 b_tok [256]     f32
    // 5 W_pos [3,256]   f32
    // 6 b_pos [256]     f32
    // 7 W_depth [256,1] f32
    // 8 b_depth [1]     f32
    const float* coords  = (const float*)d_in[1];
    const float* patches = (const float*)d_in[2];
    const float* W_tok   = (const float*)d_in[3];
    const float* b_tok   = (const float*)d_in[4];
    const float* W_pos   = (const float*)d_in[5];
    const float* b_pos   = (const float*)d_in[6];
    const float* W_dep   = (const float*)d_in[7];
    const float* b_dep   = (const float*)d_in[8];
    float* out = (float*)d_out;

    int T = in_sizes[2] / PATCH_DIM;

    fold_weights_kernel<<<3, 256>>>(W_tok, b_tok, W_pos, b_pos, W_dep, b_dep);

    int warps_per_block = 256 / 32;                 // 8 tokens per block
    int grid = (T + warps_per_block - 1) / warps_per_block;
    depth_kernel<<<grid, 256>>>(patches, coords, out, T);
}

// round 3
// speedup vs baseline: 2.9149x; 2.9149x over previous
#include <cuda_runtime.h>
#include <cuda_bf16.h>

// depth[t] = dot(patches[t], W_tok @ W_depth)
//          + dot(coords[t],  W_pos @ W_depth)
//          + (b_tok + b_pos) . W_depth + b_depth
// Kernel 1 folds the weights (now one WARP per row, coalesced).
// Kernel 2 streams patches at HBM rate, 2 tokens per warp for MLP=12.

#define PATCH_DIM 768
#define EMBED_DIM 256

__device__ float g_vtok[PATCH_DIM];
__device__ float g_vpos[3];
__device__ float g_bias;

// grid = 97 blocks * 256 threads = 776 warps.
// Warps 0..767: one row of W_tok each, lanes stride the 256 columns (coalesced).
// Warps 768..770: rows of W_pos. Warp 771: bias term.
__global__ void fold_weights_kernel(const float* __restrict__ W_tok,
                                    const float* __restrict__ b_tok,
                                    const float* __restrict__ W_pos,
                                    const float* __restrict__ b_pos,
                                    const float* __restrict__ W_dep,
                                    const float* __restrict__ b_dep) {
    int warp = (int)((blockIdx.x * blockDim.x + threadIdx.x) >> 5);
    int lane = threadIdx.x & 31;

    if (warp < PATCH_DIM) {
        const float* row = W_tok + (size_t)warp * EMBED_DIM;
        float s = 0.f;
        #pragma unroll
        for (int j = 0; j < EMBED_DIM / 32; ++j)
            s = fmaf(row[lane + 32 * j], W_dep[lane + 32 * j], s);
        #pragma unroll
        for (int off = 16; off > 0; off >>= 1)
            s += __shfl_xor_sync(0xffffffffu, s, off);
        if (lane == 0) g_vtok[warp] = s;
    } else if (warp < PATCH_DIM + 3) {
        int r = warp - PATCH_DIM;
        const float* row = W_pos + (size_t)r * EMBED_DIM;
        float s = 0.f;
        #pragma unroll
        for (int j = 0; j < EMBED_DIM / 32; ++j)
            s = fmaf(row[lane + 32 * j], W_dep[lane + 32 * j], s);
        #pragma unroll
        for (int off = 16; off > 0; off >>= 1)
            s += __shfl_xor_sync(0xffffffffu, s, off);
        if (lane == 0) g_vpos[r] = s;
    } else if (warp == PATCH_DIM + 3) {
        float s = 0.f;
        #pragma unroll
        for (int j = 0; j < EMBED_DIM / 32; ++j) {
            int e = lane + 32 * j;
            s = fmaf(b_tok[e] + b_pos[e], W_dep[e], s);
        }
        #pragma unroll
        for (int off = 16; off > 0; off >>= 1)
            s += __shfl_xor_sync(0xffffffffu, s, off);
        if (lane == 0) g_bias = s + b_dep[0];
    }
}

// 2 tokens per warp: 12 independent LDG.128 in flight per warp.
// 768 floats/token = 192 float4 = 6 float4 per lane, lane-contiguous.
__global__ __launch_bounds__(256)
void depth_kernel(const float* __restrict__ patches,
                  const float* __restrict__ coords,
                  float* __restrict__ out,
                  int T) {
    int warp = (int)((blockIdx.x * blockDim.x + threadIdx.x) >> 5);
    int lane = threadIdx.x & 31;
    int t0 = warp * 2;
    if (t0 >= T) return;
    bool hasB = (t0 + 1) < T;

    const float4* pA = (const float4*)(patches + (size_t)t0 * PATCH_DIM);
    const float4* pB = (const float4*)(patches + (size_t)(t0 + (hasB ? 1 : 0)) * PATCH_DIM);
    const float4* v  = (const float4*)g_vtok;

    float sA = 0.f, sB = 0.f;
    #pragma unroll
    for (int j = 0; j < PATCH_DIM / (4 * 32); ++j) {
        float4 a = pA[lane + 32 * j];
        float4 b = pB[lane + 32 * j];
        float4 w = v [lane + 32 * j];
        sA = fmaf(a.x, w.x, sA); sB = fmaf(b.x, w.x, sB);
        sA = fmaf(a.y, w.y, sA); sB = fmaf(b.y, w.y, sB);
        sA = fmaf(a.z, w.z, sA); sB = fmaf(b.z, w.z, sB);
        sA = fmaf(a.w, w.w, sA); sB = fmaf(b.w, w.w, sB);
    }
    #pragma unroll
    for (int off = 16; off > 0; off >>= 1) {
        sA += __shfl_xor_sync(0xffffffffu, sA, off);
        sB += __shfl_xor_sync(0xffffffffu, sB, off);
    }

    if (lane == 0) {
        const float* c3 = coords + 3 * (size_t)t0;
        out[t0] = sA + c3[0] * g_vpos[0] + c3[1] * g_vpos[1]
                     + c3[2] * g_vpos[2] + g_bias;
    }
    if (lane == 1 && hasB) {
        const float* c3 = coords + 3 * (size_t)(t0 + 1);
        out[t0 + 1] = sB + c3[0] * g_vpos[0] + c3[1] * g_vpos[1]
                         + c3[2] * g_vpos[2] + g_bias;
    }
}

extern "C" void kernel_launch(void* const* d_in, const int* in_sizes, int n_in,
                              void* d_out, int out_size) {
    const float* coords  = (const float*)d_in[1];
    const float* patches = (const float*)d_in[2];
    const float* W_tok   = (const float*)d_in[3];
    const float* b_tok   = (const float*)d_in[4];
    const float* W_pos   = (const float*)d_in[5];
    const float* b_pos   = (const float*)d_in[6];
    const float* W_dep   = (const float*)d_in[7];
    const float* b_dep   = (const float*)d_in[8];
    float* out = (float*)d_out;

    int T = in_sizes[2] / PATCH_DIM;

    // 776 warps needed -> 97 blocks of 8 warps
    fold_weights_kernel<<<97, 256>>>(W_tok, b_tok, W_pos, b_pos, W_dep, b_dep);

    // 2 tokens per warp, 8 warps per block -> 16 tokens per block
    int grid = (T + 15) / 16;
    depth_kernel<<<grid, 256>>>(patches, coords, out, T);
}

// round 4
// speedup vs baseline: 2.9360x; 1.0072x over previous
#include <cuda_runtime.h>
#include <cuda_bf16.h>

// depth[t] = dot(patches[t], W_tok @ W_depth)
//          + dot(coords[t],  W_pos @ W_depth)
//          + (b_tok + b_pos) . W_depth + b_depth
// Kernel 1: fold weights (one warp per row, coalesced).
// Kernel 2: persistent grid-stride streamer. v_tok lives in registers,
//           tokens are double-buffered so the shuffle-reduce of token t
//           overlaps the DRAM fetch of token t+nwarps.

#define PATCH_DIM 768
#define EMBED_DIM 256

__device__ float g_vtok[PATCH_DIM];
__device__ float g_vpos[3];
__device__ float g_bias;

__global__ void fold_weights_kernel(const float* __restrict__ W_tok,
                                    const float* __restrict__ b_tok,
                                    const float* __restrict__ W_pos,
                                    const float* __restrict__ b_pos,
                                    const float* __restrict__ W_dep,
                                    const float* __restrict__ b_dep) {
    int warp = (int)((blockIdx.x * blockDim.x + threadIdx.x) >> 5);
    int lane = threadIdx.x & 31;

    if (warp < PATCH_DIM) {
        const float* row = W_tok + (size_t)warp * EMBED_DIM;
        float s = 0.f;
        #pragma unroll
        for (int j = 0; j < EMBED_DIM / 32; ++j)
            s = fmaf(row[lane + 32 * j], W_dep[lane + 32 * j], s);
        #pragma unroll
        for (int off = 16; off > 0; off >>= 1)
            s += __shfl_xor_sync(0xffffffffu, s, off);
        if (lane == 0) g_vtok[warp] = s;
    } else if (warp < PATCH_DIM + 3) {
        int r = warp - PATCH_DIM;
        const float* row = W_pos + (size_t)r * EMBED_DIM;
        float s = 0.f;
        #pragma unroll
        for (int j = 0; j < EMBED_DIM / 32; ++j)
            s = fmaf(row[lane + 32 * j], W_dep[lane + 32 * j], s);
        #pragma unroll
        for (int off = 16; off > 0; off >>= 1)
            s += __shfl_xor_sync(0xffffffffu, s, off);
        if (lane == 0) g_vpos[r] = s;
    } else if (warp == PATCH_DIM + 3) {
        float s = 0.f;
        #pragma unroll
        for (int j = 0; j < EMBED_DIM / 32; ++j) {
            int e = lane + 32 * j;
            s = fmaf(b_tok[e] + b_pos[e], W_dep[e], s);
        }
        #pragma unroll
        for (int off = 16; off > 0; off >>= 1)
            s += __shfl_xor_sync(0xffffffffu, s, off);
        if (lane == 0) g_bias = s + b_dep[0];
    }
}

__device__ __forceinline__ float4 ldcs4(const float4* p) { return __ldcs(p); }

__global__ __launch_bounds__(256, 2)
void depth_kernel(const float* __restrict__ patches,
                  const float* __restrict__ coords,
                  float* __restrict__ out,
                  int T, int nwarps) {
    int gw   = (int)((blockIdx.x * blockDim.x + threadIdx.x) >> 5);
    int lane = threadIdx.x & 31;

    // Loop-invariant folded weight slice for this lane: 6 float4 in registers.
    const float4* v4 = (const float4*)g_vtok;
    float4 v0 = v4[lane +   0], v1 = v4[lane +  32], v2 = v4[lane +  64];
    float4 v3 = v4[lane +  96], v4r = v4[lane + 128], v5 = v4[lane + 160];
    float vp0 = g_vpos[0], vp1 = g_vpos[1], vp2 = g_vpos[2], bias = g_bias;

    int t = gw;
    if (t >= T) return;

    const float4* p = (const float4*)(patches + (size_t)t * PATCH_DIM);
    float4 a0 = ldcs4(p + lane +   0), a1 = ldcs4(p + lane +  32);
    float4 a2 = ldcs4(p + lane +  64), a3 = ldcs4(p + lane +  96);
    float4 a4 = ldcs4(p + lane + 128), a5 = ldcs4(p + lane + 160);

    for (;;) {
        int tn = t + nwarps;
        bool more = tn < T;
        float4 b0, b1, b2, b3, b4, b5;
        if (more) {  // prefetch next token while we reduce the current one
            const float4* pn = (const float4*)(patches + (size_t)tn * PATCH_DIM);
            b0 = ldcs4(pn + lane +   0); b1 = ldcs4(pn + lane +  32);
            b2 = ldcs4(pn + lane +  64); b3 = ldcs4(pn + lane +  96);
            b4 = ldcs4(pn + lane + 128); b5 = ldcs4(pn + lane + 160);
        }

        // two partial sums for FMA ILP
        float s0 = 0.f, s1 = 0.f;
        s0 = fmaf(a0.x, v0.x, s0); s1 = fmaf(a0.y, v0.y, s1);
        s0 = fmaf(a0.z, v0.z, s0); s1 = fmaf(a0.w, v0.w, s1);
        s0 = fmaf(a1.x, v1.x, s0); s1 = fmaf(a1.y, v1.y, s1);
        s0 = fmaf(a1.z, v1.z, s0); s1 = fmaf(a1.w, v1.w, s1);
        s0 = fmaf(a2.x, v2.x, s0); s1 = fmaf(a2.y, v2.y, s1);
        s0 = fmaf(a2.z, v2.z, s0); s1 = fmaf(a2.w, v2.w, s1);
        s0 = fmaf(a3.x, v3.x, s0); s1 = fmaf(a3.y, v3.y, s1);
        s0 = fmaf(a3.z, v3.z, s0); s1 = fmaf(a3.w, v3.w, s1);
        s0 = fmaf(a4.x, v4r.x, s0); s1 = fmaf(a4.y, v4r.y, s1);
        s0 = fmaf(a4.z, v4r.z, s0); s1 = fmaf(a4.w, v4r.w, s1);
        s0 = fmaf(a5.x, v5.x, s0); s1 = fmaf(a5.y, v5.y, s1);
        s0 = fmaf(a5.z, v5.z, s0); s1 = fmaf(a5.w, v5.w, s1);
        float s = s0 + s1;

        #pragma unroll
        for (int off = 16; off > 0; off >>= 1)
            s += __shfl_xor_sync(0xffffffffu, s, off);

        if (lane == 0) {
            const float* c3 = coords + 3 * (size_t)t;
            out[t] = s + c3[0] * vp0 + c3[1] * vp1 + c3[2] * vp2 + bias;
        }

        if (!more) break;
        t = tn;
        a0 = b0; a1 = b1; a2 = b2; a3 = b3; a4 = b4; a5 = b5;
    }
}

extern "C" void kernel_launch(void* const* d_in, const int* in_sizes, int n_in,
                              void* d_out, int out_size) {
    const float* coords  = (const float*)d_in[1];
    const float* patches = (const float*)d_in[2];
    const float* W_tok   = (const float*)d_in[3];
    const float* b_tok   = (const float*)d_in[4];
    const float* W_pos   = (const float*)d_in[5];
    const float* b_pos   = (const float*)d_in[6];
    const float* W_dep   = (const float*)d_in[7];
    const float* b_dep   = (const float*)d_in[8];
    float* out = (float*)d_out;

    int T = in_sizes[2] / PATCH_DIM;

    fold_weights_kernel<<<97, 256>>>(W_tok, b_tok, W_pos, b_pos, W_dep, b_dep);

    // Persistent grid: 2 blocks/SM * 148 SMs = 296 blocks, 8 warps each.
    int blocks = 296;
    int warps_needed = (T + 0);                 // grid-stride by warps
    int max_blocks = (warps_needed + 7) / 8;    // never launch more warps than tokens
    if (blocks > max_blocks) blocks = max_blocks;
    int nwarps = blocks * 8;
    depth_kernel<<<blocks, 256>>>(patches, coords, out, T, nwarps);
}